// round 17
// baseline (speedup 1.0000x reference)
#include <cuda_runtime.h>

// Problem constants (fixed shapes from reference)
#define BZ   16
#define CC   32
#define HH   384
#define WW   384
#define NKRN 32
#define HID  128
#define KOUT (NKRN * 9)          // 288
#define PLANE (HH * WW)          // 147456
#define NCH  (BZ * NKRN)         // 512 planes

#define CONV_TILES_X (WW / 128)  // 3
#define CONV_TILES_Y (HH / 32)   // 12
#define CONV_PER_PLANE (CONV_TILES_X * CONV_TILES_Y)       // 36
#define CONV_PER_SAMPLE (CONV_PER_PLANE * NKRN)            // 1152
#define TICKETS_PER_SAMPLE (CC + CONV_PER_SAMPLE)          // 32 pool + 1152 conv
#define TOTAL_TICKETS (BZ * TICKETS_PER_SAMPLE)            // 18944

#define NBLK 296                 // 2 per SM on 148 SMs (<= 304 slots on GB300)
#define TPB  512

// Scratch (allocation-free rule -> __device__ globals)
__device__ float g_pooled[BZ * CC];
__device__ float g_kernels[BZ * KOUT];
__device__ int   g_ticket;
__device__ int   g_poolcnt[BZ];
__device__ int   g_flag[BZ];

// ---------------------------------------------------------------------------
// Reset kernel: zero the coordination state each call (graph-replayable).
// ---------------------------------------------------------------------------
__global__ void reset_kernel() {
    if (threadIdx.x == 0) g_ticket = 0;
    if (threadIdx.x < BZ) { g_poolcnt[threadIdx.x] = 0; g_flag[threadIdx.x] = 0; }
}

// ---------------------------------------------------------------------------
// Fused persistent kernel.
// Ticket layout (sample-major): for each sample b:
//   tickets [0,32)     : pool one (b,c) plane each; last finisher runs the MLP
//                        for b and releases g_flag[b].
//   tickets [32,1184)  : conv tiles for b (spin on g_flag[b] first).
// Deadlock-free: pool tickets of b always precede conv tickets of b in the
// queue, so any block spinning on conv(b) implies the pool(b) tickets are
// already claimed by blocks that make unconditional progress.
// Coherence: cross-block data read with __ldcg (L2), released with
// __threadfence + device atomic (no launch-boundary L1 flush inside a kernel).
// ---------------------------------------------------------------------------
__global__ __launch_bounds__(TPB, 2)
void fused_kernel(const float* __restrict__ x,
                  const float* __restrict__ w1,
                  const float* __restrict__ b1,
                  const float* __restrict__ w2,
                  const float* __restrict__ b2,
                  float* __restrict__ out) {
    __shared__ float smem[34][136];      // conv tile
    __shared__ float sh[HID];            // MLP hidden
    __shared__ float sp[CC];             // MLP pooled inputs
    __shared__ float ws[16];             // pool warp partials
    __shared__ int   s_t;
    __shared__ int   s_do_mlp;

    const int tid = threadIdx.x;

    while (true) {
        if (tid == 0) s_t = atomicAdd(&g_ticket, 1);
        __syncthreads();                 // broadcast ticket; also fences smem reuse
        const int t = s_t;
        if (t >= TOTAL_TICKETS) return;  // uniform exit

        const int b = t / TICKETS_PER_SAMPLE;
        const int r = t - b * TICKETS_PER_SAMPLE;

        if (r < CC) {
            // ---------------- pool one plane (b, c=r) ----------------
            const int ch = b * CC + r;
            const float4* __restrict__ p =
                reinterpret_cast<const float4*>(x + (size_t)ch * PLANE);
            float4 acc = make_float4(0.f, 0.f, 0.f, 0.f);
            #pragma unroll 4
            for (int i = tid; i < PLANE / 4; i += TPB) {
                float4 v = __ldcs(&p[i]);
                acc.x += v.x; acc.y += v.y; acc.z += v.z; acc.w += v.w;
            }
            float s = (acc.x + acc.y) + (acc.z + acc.w);
            #pragma unroll
            for (int o = 16; o; o >>= 1) s += __shfl_xor_sync(0xffffffffu, s, o);
            const int wid = tid >> 5, lid = tid & 31;
            if (lid == 0) ws[wid] = s;
            __syncthreads();
            if (tid == 0) {
                float tt = 0.f;
                #pragma unroll
                for (int i = 0; i < 16; i++) tt += ws[i];
                g_pooled[ch] = tt * (1.0f / PLANE);
                __threadfence();
                const int old = atomicAdd(&g_poolcnt[b], 1);
                s_do_mlp = (old == CC - 1);
            }
            __syncthreads();

            if (s_do_mlp) {
                // ---------------- MLP for sample b ----------------
                if (tid < CC) sp[tid] = __ldcg(&g_pooled[b * CC + tid]);
                __syncthreads();
                if (tid < HID) {
                    float a = b1[tid];
                    #pragma unroll
                    for (int c = 0; c < CC; c++)
                        a = fmaf(sp[c], w1[c * HID + tid], a);
                    sh[tid] = fmaxf(a, 0.f);
                }
                __syncthreads();
                if (tid < KOUT) {
                    float a = b2[tid];
                    #pragma unroll 8
                    for (int h = 0; h < HID; h++)
                        a = fmaf(sh[h], w2[h * KOUT + tid], a);
                    g_kernels[b * KOUT + tid] = a;
                }
                __syncthreads();
                if (tid == 0) {
                    __threadfence();
                    atomicExch(&g_flag[b], 1);
                }
            }
        } else {
            // ---------------- conv tile ----------------
            const int idx = r - CC;
            const int bx  = idx % CONV_TILES_X;
            const int by  = (idx / CONV_TILES_X) % CONV_TILES_Y;
            const int k   = idx / CONV_PER_PLANE;
            const int ch  = b * NKRN + k;

            // wait for this sample's kernels
            if (tid == 0) {
                while (atomicAdd(&g_flag[b], 0) == 0) __nanosleep(64);
                __threadfence();
            }
            __syncthreads();

            const float* __restrict__ xin = x + (size_t)ch * PLANE;
            float*       __restrict__ op  = out + (size_t)ch * PLANE;

            const int gx0 = bx * 32 - 1;             // float4-col base (halo)
            const int gy0 = by * 32 - 1;             // row base (halo)

            // fill smem tile (zero outside image): 34*34 float4 / 512 thr
            #pragma unroll
            for (int it = 0; it < 3; it++) {
                const int i = tid + it * TPB;
                if (i < 34 * 34) {
                    const int rr = i / 34;
                    const int fc = i - rr * 34;
                    const int gy = gy0 + rr;
                    const int g4 = gx0 + fc;
                    float4 v = make_float4(0.f, 0.f, 0.f, 0.f);
                    if ((unsigned)gy < (unsigned)HH && (unsigned)g4 < (unsigned)(WW / 4))
                        v = *reinterpret_cast<const float4*>(xin + (size_t)gy * WW + g4 * 4);
                    *reinterpret_cast<float4*>(&smem[rr][fc * 4]) = v;
                }
            }

            // per-plane 3x3 weights (L2 read — MUST bypass L1 in-kernel)
            float wk[9];
            #pragma unroll
            for (int i = 0; i < 9; i++) wk[i] = __ldcg(&g_kernels[ch * 9 + i]);

            __syncthreads();

            const int j   = tid & 31;                // float4 output column
            const int tr  = tid >> 5;                // thread-row 0..15
            const int cb  = j * 4;                   // smem float col base
            const int sr0 = tr * 2;                  // first smem row of window

            float r0v[12], r1v[12], r2v[12];

            #define LOADROW(SR, DST)                                               \
                do {                                                               \
                    float4 _a = *reinterpret_cast<const float4*>(&smem[SR][cb]);   \
                    float4 _b = *reinterpret_cast<const float4*>(&smem[SR][cb+4]); \
                    float4 _c = *reinterpret_cast<const float4*>(&smem[SR][cb+8]); \
                    (DST)[0]=_a.x; (DST)[1]=_a.y; (DST)[2]=_a.z; (DST)[3]=_a.w;    \
                    (DST)[4]=_b.x; (DST)[5]=_b.y; (DST)[6]=_b.z; (DST)[7]=_b.w;    \
                    (DST)[8]=_c.x; (DST)[9]=_c.y; (DST)[10]=_c.z; (DST)[11]=_c.w;  \
                } while (0)

            #define DOROW(RA, RB, RC, OROW)                                        \
                do {                                                               \
                    float o[4];                                                    \
                    _Pragma("unroll")                                              \
                    for (int kk = 0; kk < 4; kk++) {                               \
                        float a;                                                   \
                        a = wk[0] * (RA)[kk + 3];                                  \
                        a = fmaf(wk[1], (RA)[kk + 4], a);                          \
                        a = fmaf(wk[2], (RA)[kk + 5], a);                          \
                        a = fmaf(wk[3], (RB)[kk + 3], a);                          \
                        a = fmaf(wk[4], (RB)[kk + 4], a);                          \
                        a = fmaf(wk[5], (RB)[kk + 5], a);                          \
                        a = fmaf(wk[6], (RC)[kk + 3], a);                          \
                        a = fmaf(wk[7], (RC)[kk + 4], a);                          \
                        a = fmaf(wk[8], (RC)[kk + 5], a);                          \
                        o[kk] = a;                                                 \
                    }                                                              \
                    __stcs(reinterpret_cast<float4*>(op + (size_t)(OROW) * WW + ocol), \
                           make_float4(o[0], o[1], o[2], o[3]));                   \
                } while (0)

            LOADROW(sr0 + 0, r0v);
            LOADROW(sr0 + 1, r1v);
            LOADROW(sr0 + 2, r2v);

            const int orow0 = by * 32 + tr * 2;
            const int ocol  = bx * 128 + cb;

            DOROW(r0v, r1v, r2v, orow0);
            LOADROW(sr0 + 3, r0v);
            DOROW(r1v, r2v, r0v, orow0 + 1);

            #undef DOROW
            #undef LOADROW
        }
    }
}

// ---------------------------------------------------------------------------
extern "C" void kernel_launch(void* const* d_in, const int* in_sizes, int n_in,
                              void* d_out, int out_size) {
    const float* x  = (const float*)d_in[0];
    const float* w1 = (const float*)d_in[1];
    const float* b1 = (const float*)d_in[2];
    const float* w2 = (const float*)d_in[3];
    const float* b2 = (const float*)d_in[4];
    float* out = (float*)d_out;

    reset_kernel<<<1, 32>>>();
    fused_kernel<<<NBLK, TPB>>>(x, w1, b1, w2, b2, out);
}